// round 13
// baseline (speedup 1.0000x reference)
#include <cuda_runtime.h>
#include <math.h>

#define ATOMS 48
#define CAP   48           // per-species bucket capacity (worst case)
#define BLK   128
#define APB   2            // atoms per block
#define BSTR  193          // padded per-atom bucket stride (4*CAP + 1)
#define GBS   129          // gbuf stride (chunk 128 + pad)

// cos/sin of SHF_Z[z] = (2z+1)*pi/16
__device__ __constant__ float COSZ[8] = {
     0.98078528040323044913f,  0.83146961230254523708f,
     0.55557023301960222474f,  0.19509032201612826785f,
    -0.19509032201612826785f, -0.55557023301960222474f,
    -0.83146961230254523708f, -0.98078528040323044913f };
__device__ __constant__ float SINZ[8] = {
     0.19509032201612826785f,  0.55557023301960222474f,
     0.83146961230254523708f,  0.98078528040323044913f,
     0.98078528040323044913f,  0.83146961230254523708f,
     0.55557023301960222474f,  0.19509032201612826785f };

// PAIR_IDX for 4 species (upper-triangular enumeration, symmetric)
__device__ __constant__ int PAIRT[4][4] = {
    {0,1,2,3},{1,4,5,6},{2,5,7,8},{3,6,8,9} };

__global__ void __launch_bounds__(BLK)
aev_kernel(const int* __restrict__ species, const float* __restrict__ coords,
           float* __restrict__ aev_out, float* __restrict__ sp_out)
{
    const int i0  = blockIdx.x * APB;  // first atom of this block
    const int b   = blockIdx.y;        // batch
    const int A   = ATOMS;
    const int tid = threadIdx.x;

    __shared__ float cx[ATOMS], cy[ATOMS], cz[ATOMS];
    __shared__ int   sp[ATOMS];
    __shared__ float4 bvec[APB*BSTR];   // (vx, vy, vz, d) angular buckets
    __shared__ float2 bsc[APB*BSTR];    // (sqrt(0.95)/d, fc_a)
    __shared__ float2 rpak[APB*4*CAP];  // (d, 0.25*fc_r) radial buckets
    __shared__ int   cnt[APB][4], rcnt[APB][4];
    __shared__ int   jlistA[APB][CAP];  // per-atom: slot(8b) | sj<<8
    __shared__ int   Mcnt[APB];
    __shared__ int   gcnt[2*10];        // per-chunk class counters (atom,pair)
    __shared__ unsigned char glistP[2*10][BLK];
    __shared__ float gbuf[32 * GBS];    // [feature][local group] scratch

    const float* cb = coords + (size_t)b * A * 3;
    if (tid < A) {
        cx[tid] = cb[tid*3 + 0];
        cy[tid] = cb[tid*3 + 1];
        cz[tid] = cb[tid*3 + 2];
        sp[tid] = species[b*A + tid];
    }
    if (tid < 8)  { cnt[tid>>2][tid&3] = 0; rcnt[tid>>2][tid&3] = 0; }
    if (tid < APB) Mcnt[tid] = 0;
    __syncthreads();

    // ---- phase 1: distances, bucketed neighbor lists (2 atoms x 48 j) ----
    if (tid < APB * A) {
        const int a  = tid / A;
        const int j  = tid - a * A;
        const int ia = i0 + a;
        if (j != ia) {
            float dx = cx[j] - cx[ia];
            float dy = cy[j] - cy[ia];
            float dz = cz[j] - cz[ia];
            float d  = sqrtf(dx*dx + dy*dy + dz*dz);
            int   s  = sp[j];
            if (d <= 5.2f) {
                float fcr = 0.5f * cospif(d / 5.2f) + 0.5f;
                int m = atomicAdd(&rcnt[a][s], 1);
                rpak[a*4*CAP + s*CAP + m] = make_float2(d, 0.25f * fcr);
            }
            if (d <= 3.5f) {
                float fca = 0.5f * cospif(d / 3.5f) + 0.5f;
                int m    = atomicAdd(&cnt[a][s], 1);
                int slot = s*CAP + m;                   // < 192, fits 8 bits
                bvec[a*BSTR + slot] = make_float4(dx, dy, dz, d);
                // sqrt(0.95)/d so that js.x*ks.x carries the 0.95 factor
                bsc[a*BSTR + slot]  = make_float2(0.97467943448089633f / d, fca);
                int pos = atomicAdd(&Mcnt[a], 1);
                jlistA[a][pos] = slot | (s << 8);
            }
        }
    }
    __syncthreads();

    // ---- phase 2/3 fused: chunks of 128 groups; gbuf STS flush; ----
    // Group order: atom-major, then sk-major, then j — all groups of one
    // (atom, sk) class are contiguous, and every group in a class has the
    // SAME inner trip count cnt[a][sk] => warp-convergent k-loops.
    // Ordered-pair sum with weight fc_j*fc_k equals the reference's
    // unordered sum with weight 2*fc_j*fc_k (integrand symmetric in j,k).
    const float K1 = __expf(-6.76f);   // exp step for the f2 recurrence
    const int M0 = Mcnt[0];
    const int M1 = Mcnt[1];
    const int G0 = 4 * M0;
    const int G  = G0 + 4 * M1;

    float racc[5];                     // angular features, 640 over 128 threads
    #pragma unroll
    for (int it = 0; it < 5; it++) racc[it] = 0.0f;

    for (int c0 = 0; c0 < G; c0 += BLK) {
        if (tid < 20) gcnt[tid] = 0;
        __syncthreads();

        const int g = c0 + tid;
        if (g < G) {
            const int a    = (g >= G0) ? 1 : 0;
            const int g2   = g - a * G0;
            const int Ma   = (a == 0) ? M0 : M1;
            const int sk   = g2 / Ma;
            const int jidx = g2 - sk * Ma;
            const int jid   = jlistA[a][jidx];
            const int jslot = jid & 255;
            const int sj    = jid >> 8;
            const int ab    = a * BSTR;

            const float4 jv = bvec[ab + jslot];
            const float2 js = bsc[ab + jslot];

            float acc[32];
            #pragma unroll
            for (int q = 0; q < 32; q++) acc[q] = 0.0f;

            const int n    = cnt[a][sk];
            const int base = ab + sk * CAP;
            #pragma unroll 2
            for (int m = 0; m < n; m++) {
                const int kslot = base + m;
                float4 kv = bvec[kslot];
                float2 ks = bsc[kslot];
                float dot = jv.x*kv.x + jv.y*kv.y + jv.z*kv.z;
                float ct  = dot * js.x * ks.x;            // carries 0.95
                float st  = sqrtf(fmaxf(1.0f - ct*ct, 0.0f));
                float avg = 0.5f * (jv.w + kv.w);
                float wgt = (kslot == ab + jslot) ? 0.0f : js.y * ks.y;

                // f2v[a] = w*exp(-8*(u-0.65a)^2), exact geometric recurrence
                float u   = avg - 0.9f;
                float f0  = wgt * __expf(-8.0f * u * u);
                float r   = __expf(fmaf(10.4f, u, -3.38f));
                float f1v = f0 * r;
                float r2  = r * K1;
                float f2v = f1v * r2;
                float r3  = r2 * K1;
                float f3v = f2v * r3;

                #pragma unroll
                for (int z = 0; z < 8; z++) {
                    float c   = ct * COSZ[z] + st * SINZ[z];
                    float b1  = 0.5f + 0.5f * c;
                    float b2  = b1 * b1;
                    float b4  = b2 * b2;
                    float b8  = b4 * b4;
                    float b16 = b8 * b8;
                    float f1  = b16 * b16;                // ((1+c)/2)^32
                    acc[0*8 + z] += f0  * f1;
                    acc[1*8 + z] += f1v * f1;
                    acc[2*8 + z] += f2v * f1;
                    acc[3*8 + z] += f3v * f1;
                }
            }

            const int pcls = a * 10 + PAIRT[sj][sk];
            int mm = atomicAdd(&gcnt[pcls], 1);
            glistP[pcls][mm] = (unsigned char)tid;
            #pragma unroll
            for (int q = 0; q < 32; q++)
                gbuf[q * GBS + tid] = acc[q];   // conflict-free: lanes consec
        }
        __syncthreads();

        // gather: feature f = it*BLK + tid over (atom, pair-class, q)
        #pragma unroll
        for (int it = 0; it < 5; it++) {
            const int f = it * BLK + tid;      // < 640
            const int a    = f / 320;
            const int rem  = f - a * 320;
            const int pcls = a * 10 + (rem >> 5);
            const int q    = rem & 31;
            const int nm = gcnt[pcls];
            float s = 0.0f;
            for (int m = 0; m < nm; m++) {
                int lg = glistP[pcls][m];      // broadcast
                s += gbuf[q * GBS + lg];       // conflict-free: lanes consec q
            }
            racc[it] += s;
        }
        __syncthreads();
    }

    // ---- output ----
    // radial: feature (a, s, r) — exactly 128 features, one per thread
    {
        const int a = tid >> 6;
        const int s = (tid >> 4) & 3;
        const int r = tid & 15;
        const float shf = 0.9f + 0.26875f * (float)r;
        const int n = rcnt[a][s];
        float acc = 0.0f;
        for (int m = 0; m < n; m++) {
            float2 v = rpak[a*4*CAP + s*CAP + m];  // broadcast in 16-lane grp
            float u = v.x - shf;
            acc += v.y * __expf(-16.0f * u * u);
        }
        aev_out[(size_t)(b * A + i0 + a) * 384 + s*16 + r] = acc;
    }

    // angular: write register accumulators
    #pragma unroll
    for (int it = 0; it < 5; it++) {
        const int f = it * BLK + tid;
        const int a   = f / 320;
        const int rem = f - a * 320;
        aev_out[(size_t)(b * A + i0 + a) * 384 + 64 + rem] = racc[it];
    }

    if (sp_out != nullptr && tid < APB)
        sp_out[b * A + i0 + tid] = (float)sp[i0 + tid];
}

extern "C" void kernel_launch(void* const* d_in, const int* in_sizes, int n_in,
                              void* d_out, int out_size)
{
    const int*   species = (const int*)d_in[0];
    const float* coords  = (const float*)d_in[1];

    const int BA = in_sizes[0];     // B*A
    const int A  = ATOMS;           // 48 per reference
    const int B  = BA / A;
    const int aev_total = BA * 384;

    float* out    = (float*)d_out;
    float* sp_out = nullptr;
    float* aev    = out;
    if (out_size >= aev_total + BA) {   // tuple output: species first, then aevs
        sp_out = out;
        aev    = out + BA;
    }

    dim3 grid(A / APB, B);
    aev_kernel<<<grid, BLK>>>(species, coords, aev, sp_out);
}

// round 14
// speedup vs baseline: 1.2222x; 1.2222x over previous
#include <cuda_runtime.h>
#include <math.h>

#define ATOMS 48
#define CAP   48           // per-species bucket capacity (worst case)
#define BLK   128
#define APB   2            // atoms per block
#define BSTR  193          // padded per-atom bucket stride (4*CAP + 1)
#define GBS   129          // gbuf stride (chunk 128 + pad)
#define GLMAX 384          // worst-case group count

// cos/sin of SHF_Z[z] = (2z+1)*pi/16
__device__ __constant__ float COSZ[8] = {
     0.98078528040323044913f,  0.83146961230254523708f,
     0.55557023301960222474f,  0.19509032201612826785f,
    -0.19509032201612826785f, -0.55557023301960222474f,
    -0.83146961230254523708f, -0.98078528040323044913f };
__device__ __constant__ float SINZ[8] = {
     0.19509032201612826785f,  0.55557023301960222474f,
     0.83146961230254523708f,  0.98078528040323044913f,
     0.98078528040323044913f,  0.83146961230254523708f,
     0.55557023301960222474f,  0.19509032201612826785f };

// PAIR_IDX for 4 species (upper-triangular enumeration, symmetric)
__device__ __constant__ int PAIRT[4][4] = {
    {0,1,2,3},{1,4,5,6},{2,5,7,8},{3,6,8,9} };

__global__ void __launch_bounds__(BLK)
aev_kernel(const int* __restrict__ species, const float* __restrict__ coords,
           float* __restrict__ aev_out, float* __restrict__ sp_out)
{
    const int i0  = blockIdx.x * APB;  // first atom of this block
    const int b   = blockIdx.y;        // batch
    const int A   = ATOMS;
    const int tid = threadIdx.x;

    __shared__ float cx[ATOMS], cy[ATOMS], cz[ATOMS];
    __shared__ int   sp[ATOMS];
    __shared__ float4 bvec[APB*BSTR];   // (vx, vy, vz, x=d/2-0.45)
    __shared__ float4 bsc[APB*BSTR];    // (sqrt(.95)/d, sqrt(2)*fc_a, E, R)
    __shared__ float2 rpak[APB*4*CAP];  // (d, 0.25*fc_r) radial buckets
    __shared__ int   cnt[APB][4], rcnt[APB][4];
    __shared__ int   jlistA[APB][CAP];  // per-atom: slot(8b) | sj<<8
    __shared__ int   Mcnt[APB];
    __shared__ int   glist[GLMAX];      // slot | sj<<8 | sk<<10 | a<<12
    __shared__ int   Gtot;
    __shared__ int   gcnt[2*10];        // per-chunk class counters (atom,pair)
    __shared__ unsigned char glistP[2*10][BLK];
    __shared__ float gbuf[32 * GBS];    // [feature][local group] scratch

    const float* cb = coords + (size_t)b * A * 3;
    if (tid < A) {
        cx[tid] = cb[tid*3 + 0];
        cy[tid] = cb[tid*3 + 1];
        cz[tid] = cb[tid*3 + 2];
        sp[tid] = species[b*A + tid];
    }
    if (tid < 8)  { cnt[tid>>2][tid&3] = 0; rcnt[tid>>2][tid&3] = 0; }
    if (tid < APB) Mcnt[tid] = 0;
    if (tid == 2)  Gtot = 0;
    __syncthreads();

    // ---- phase 1: distances, bucketed neighbor lists (2 atoms x 48 j) ----
    if (tid < APB * A) {
        const int a  = tid / A;
        const int j  = tid - a * A;
        const int ia = i0 + a;
        if (j != ia) {
            float dx = cx[j] - cx[ia];
            float dy = cy[j] - cy[ia];
            float dz = cz[j] - cz[ia];
            float d  = sqrtf(dx*dx + dy*dy + dz*dz);
            int   s  = sp[j];
            if (d <= 5.2f) {
                float fcr = 0.5f * cospif(d / 5.2f) + 0.5f;
                int m = atomicAdd(&rcnt[a][s], 1);
                rpak[a*4*CAP + s*CAP + m] = make_float2(d, 0.25f * fcr);
            }
            if (d <= 3.5f) {
                float fca = 0.5f * cospif(d / 3.5f) + 0.5f;
                int m    = atomicAdd(&cnt[a][s], 1);
                int slot = s*CAP + m;                   // < 192, fits 8 bits
                float x  = 0.5f * d - 0.45f;            // u_pair = x_j + x_k
                bvec[a*BSTR + slot] = make_float4(dx, dy, dz, x);
                // E = exp(-8x^2), R = exp(10.4x - 1.69): factored Gaussians
                bsc[a*BSTR + slot]  = make_float4(
                    0.97467943448089633f / d,           // sqrt(0.95)/d
                    1.41421356237309515f * fca,         // sqrt(2)*fc
                    __expf(-8.0f * x * x),
                    __expf(fmaf(10.4f, x, -1.69f)));
                int pos = atomicAdd(&Mcnt[a], 1);
                jlistA[a][pos] = slot | (s << 8);
            }
        }
    }
    __syncthreads();

    // ---- phase 1.5: expand unordered group list: (j, sk) with sk <= sj ----
    {
        const int M0 = Mcnt[0];
        const int M1 = Mcnt[1];
        if (tid < M0 + M1) {
            const int a    = (tid >= M0) ? 1 : 0;
            const int jidx = tid - a * M0;
            const int jid  = jlistA[a][jidx];
            const int sj   = jid >> 8;
            int pos = atomicAdd(&Gtot, sj + 1);
            for (int sk = 0; sk <= sj; sk++)
                glist[pos + sk] = (jid & 255) | (sj << 8) | (sk << 10) | (a << 12);
        }
    }
    __syncthreads();

    // ---- phase 2/3 fused: chunks of 128 groups; gbuf STS flush. ----
    // Each unordered pair {j,k} inside the angular cutoff is evaluated
    // exactly once (sk<sj: full bucket; sk==sj: k after j in bucket) with
    // weight 2*fc_j*fc_k (the 2 carried by the sqrt(2)-folded fc's).
    const float K1 = __expf(-6.76f);   // exp step for the f2 recurrence
    const int G = Gtot;

    float racc[5];                     // angular features, 640 over 128 threads
    #pragma unroll
    for (int it = 0; it < 5; it++) racc[it] = 0.0f;

    for (int c0 = 0; c0 < G; c0 += BLK) {
        if (tid < 20) gcnt[tid] = 0;
        __syncthreads();

        const int g = c0 + tid;
        if (g < G) {
            const int jid   = glist[g];
            const int jslot = jid & 255;
            const int sj    = (jid >> 8) & 3;
            const int sk    = (jid >> 10) & 3;
            const int a     = jid >> 12;
            const int ab    = a * BSTR;

            const float4 jv = bvec[ab + jslot];
            const float4 js = bsc[ab + jslot];

            float acc[32];
            #pragma unroll
            for (int q = 0; q < 32; q++) acc[q] = 0.0f;

            const int n    = cnt[a][sk];
            const int base = ab + sk * CAP;
            const int m0   = (sk == sj) ? (jslot - sk*CAP + 1) : 0;
            #pragma unroll 2
            for (int m = m0; m < n; m++) {
                const int kslot = base + m;
                float4 kv = bvec[kslot];
                float4 ks = bsc[kslot];
                float dot = jv.x*kv.x + jv.y*kv.y + jv.z*kv.z;
                float ct  = dot * js.x * ks.x;            // carries 0.95
                float st  = sqrtf(fmaxf(1.0f - ct*ct, 0.0f));
                float xy  = jv.w * kv.w;

                // f2v[a] = 2*fc*fc*exp(-8*(u-0.65a)^2) via factored
                // Gaussians + exact geometric recurrence (1 exp + 1 sqrt)
                float g0  = __expf(-16.0f * xy);
                float f0  = js.y * ks.y * js.z * ks.z * g0;
                float r   = js.w * ks.w;
                float f1v = f0 * r;
                float r2  = r * K1;
                float f2v = f1v * r2;
                float r3  = r2 * K1;
                float f3v = f2v * r3;

                #pragma unroll
                for (int z = 0; z < 8; z++) {
                    float c   = ct * COSZ[z] + st * SINZ[z];
                    float b1  = 0.5f + 0.5f * c;
                    float b2  = b1 * b1;
                    float b4  = b2 * b2;
                    float b8  = b4 * b4;
                    float b16 = b8 * b8;
                    float f1  = b16 * b16;                // ((1+c)/2)^32
                    acc[0*8 + z] += f0  * f1;
                    acc[1*8 + z] += f1v * f1;
                    acc[2*8 + z] += f2v * f1;
                    acc[3*8 + z] += f3v * f1;
                }
            }

            const int pcls = a * 10 + PAIRT[sj][sk];
            int mm = atomicAdd(&gcnt[pcls], 1);
            glistP[pcls][mm] = (unsigned char)tid;
            #pragma unroll
            for (int q = 0; q < 32; q++)
                gbuf[q * GBS + tid] = acc[q];   // conflict-free: lanes consec
        }
        __syncthreads();

        // gather: feature f = it*BLK + tid over (atom, pair-class, q)
        #pragma unroll
        for (int it = 0; it < 5; it++) {
            const int f = it * BLK + tid;      // < 640
            const int a    = f / 320;
            const int rem  = f - a * 320;
            const int pcls = a * 10 + (rem >> 5);
            const int q    = rem & 31;
            const int nm = gcnt[pcls];
            float s = 0.0f;
            for (int m = 0; m < nm; m++) {
                int lg = glistP[pcls][m];      // broadcast
                s += gbuf[q * GBS + lg];       // conflict-free: lanes consec q
            }
            racc[it] += s;
        }
        __syncthreads();
    }

    // ---- output ----
    // radial: feature (a, s, r) — exactly 128 features, one per thread
    {
        const int a = tid >> 6;
        const int s = (tid >> 4) & 3;
        const int r = tid & 15;
        const float shf = 0.9f + 0.26875f * (float)r;
        const int n = rcnt[a][s];
        float acc = 0.0f;
        for (int m = 0; m < n; m++) {
            float2 v = rpak[a*4*CAP + s*CAP + m];  // broadcast in 16-lane grp
            float u = v.x - shf;
            acc += v.y * __expf(-16.0f * u * u);
        }
        aev_out[(size_t)(b * A + i0 + a) * 384 + s*16 + r] = acc;
    }

    // angular: write register accumulators
    #pragma unroll
    for (int it = 0; it < 5; it++) {
        const int f = it * BLK + tid;
        const int a   = f / 320;
        const int rem = f - a * 320;
        aev_out[(size_t)(b * A + i0 + a) * 384 + 64 + rem] = racc[it];
    }

    if (sp_out != nullptr && tid < APB)
        sp_out[b * A + i0 + tid] = (float)sp[i0 + tid];
}

extern "C" void kernel_launch(void* const* d_in, const int* in_sizes, int n_in,
                              void* d_out, int out_size)
{
    const int*   species = (const int*)d_in[0];
    const float* coords  = (const float*)d_in[1];

    const int BA = in_sizes[0];     // B*A
    const int A  = ATOMS;           // 48 per reference
    const int B  = BA / A;
    const int aev_total = BA * 384;

    float* out    = (float*)d_out;
    float* sp_out = nullptr;
    float* aev    = out;
    if (out_size >= aev_total + BA) {   // tuple output: species first, then aevs
        sp_out = out;
        aev    = out + BA;
    }

    dim3 grid(A / APB, B);
    aev_kernel<<<grid, BLK>>>(species, coords, aev, sp_out);
}